// round 11
// baseline (speedup 1.0000x reference)
#include <cuda_runtime.h>
#include <cstdint>

#define H_N      1500
#define G4       6000
#define T_STEPS  4096
#define MLP_HID_N 1875
#define OUT_N    20
#define IN_N     20
#define NCTA     125         // 125 CTAs x 12 units = 1500
#define NTHREADS 512
#define NU       12
#define NROWS    48
#define NB       16          // plane-B rows (smem)
#define NREP     4           // h replication factor
#define DEPTH    4           // h ring depth
#define WPAD_B   1508
#define NCHUNK   24          // 375 = 7*24 + 9*23

// ---------------- device scratch ----------------
__device__ float    g_xp[(size_t)T_STEPS * G4];
__device__ float    g_hrep[DEPTH][NREP][1504];   // 4-deep ring, replicated
__device__ float    g_hid[MLP_HID_N];
__device__ unsigned g_done[128 * 8];             // per-CTA step flag, stride 8 words
__device__ unsigned g_cnt[128];                  // [0]=backpressure counter, [64]=mlp

#define FMA2(acc, a, b) \
    asm("fma.rn.f32x2 %0, %1, %2, %0;" : "+l"(acc) : "l"(a), "l"(b))

__device__ __forceinline__ float sigmoid_f(float x) {
    return __fdividef(1.f, 1.f + __expf(-x));
}
__device__ __forceinline__ float tanh_f(float x) {
    return __fdividef(2.f, 1.f + __expf(-2.f * x)) - 1.f;
}

__device__ __forceinline__ void cp_async16(uint32_t dst, const float* src) {
    asm volatile("cp.async.cg.shared.global [%0], [%1], 16;" :: "r"(dst), "l"(src));
}
#define CP_COMMIT() asm volatile("cp.async.commit_group;" ::: "memory")
#define CP_WAIT3()  asm volatile("cp.async.wait_group 3;" ::: "memory")

__device__ __forceinline__ unsigned ld_acq_g(const unsigned* p) {
    unsigned v;
    asm volatile("ld.acquire.gpu.global.u32 %0, [%1];" : "=r"(v) : "l"(p) : "memory");
    return v;
}
__device__ __forceinline__ void st_rel_g(unsigned* p, unsigned v) {
    asm volatile("st.release.gpu.global.u32 [%0], %1;" :: "l"(p), "r"(v) : "memory");
}
__device__ __forceinline__ void red_rel_g(unsigned* p) {
    asm volatile("red.release.gpu.global.add.u32 [%0], 1;" :: "l"(p) : "memory");
}
__device__ __forceinline__ void st_rel_s(uint32_t a, unsigned v) {
    asm volatile("st.release.cta.shared.u32 [%0], %1;" :: "r"(a), "r"(v) : "memory");
}
__device__ __forceinline__ unsigned ld_acq_s(uint32_t a) {
    unsigned v;
    asm volatile("ld.acquire.cta.shared.u32 %0, [%1];" : "=r"(v) : "r"(a) : "memory");
    return v;
}

// ---------------- pre: init state + x_proj ----------------
__global__ void pre_kernel(const float* __restrict__ inp,
                           const float* __restrict__ W_ih,
                           const float* __restrict__ b_ih,
                           const float* __restrict__ b_hh) {
    __shared__ float Wsm[256 * 21];
    __shared__ float bsm[256];
    __shared__ float insm[128 * IN_N];
    int tid = threadIdx.x;
    int r0 = blockIdx.x * 256;
    int t0 = blockIdx.y * 128;

    if (blockIdx.x == 0 && blockIdx.y == 0) {
        float* hz = &g_hrep[0][0][0];
        for (int i = tid; i < DEPTH * NREP * 1504; i += 256) hz[i] = 0.f;
        for (int i = tid; i < 128 * 8; i += 256) g_done[i] = 0u;
        for (int i = tid; i < 128; i += 256) g_cnt[i] = 0u;
    }

    for (int i = tid; i < 256 * IN_N; i += 256) {
        int rr = i / IN_N, k = i % IN_N;
        int row = r0 + rr;
        Wsm[rr * 21 + k] = (row < G4) ? W_ih[row * IN_N + k] : 0.f;
    }
    {
        int row = r0 + tid;
        bsm[tid] = (row < G4) ? (b_ih[row] + b_hh[row]) : 0.f;
    }
    for (int i = tid; i < 128 * IN_N; i += 256)
        insm[i] = inp[t0 * IN_N + i];
    __syncthreads();

    int row = r0 + tid;
    if (row < G4) {
        const float* wrow = &Wsm[tid * 21];
        float bias = bsm[tid];
        for (int tt = 0; tt < 128; tt++) {
            const float* ir = &insm[tt * IN_N];
            float acc = bias;
            #pragma unroll
            for (int k = 0; k < IN_N; k++) acc += ir[k] * wrow[k];
            g_xp[(size_t)(t0 + tt) * G4 + row] = acc;
        }
    }
}

// ---------------- persistent LSTM + MLP ----------------
__global__ void __launch_bounds__(NTHREADS, 1)
lstm_kernel(const float* __restrict__ W_hh,
            const float* __restrict__ W1,
            const float* __restrict__ b1,
            const float* __restrict__ W2,
            const float* __restrict__ b2,
            float* __restrict__ out) {
    extern __shared__ float smem[];
    float* Wb_s  = smem;                         // NB * WPAD_B
    float* h_s   = Wb_s + NB * WPAD_B;           // 1504
    float* part  = h_s + 1504;                   // NROWS * 17
    float* xpr   = part + NROWS * 17;            // 4 * 48
    float* c_s   = xpr + 4 * NROWS;              // 16
    unsigned* uflag = (unsigned*)(c_s + 16);     // [0] = backpressure bound

    const int tid  = threadIdx.x;
    const int lane = tid & 31;
    const int w    = tid >> 5;
    const int b    = blockIdx.x;
    const int u0   = b * NU;

    const int NK    = (w < 7) ? 24 : 23;
    const int start = (w < 7) ? w * 24 : 168 + (w - 7) * 23;

    // producer-CTA span for this warp's columns [start*4, start*4+NK*4)
    const int c0 = (start * 4) / NU;
    const int c1 = (start * 4 + NK * 4 - 1) / NU;      // span <= 9 CTAs

    const uint32_t bp_addr = (uint32_t)__cvta_generic_to_shared(uflag);

    // ---- preload plane-B weights (rows 32..47) into smem ----
    for (int idx = tid; idx < NB * 377; idx += NTHREADS) {
        int r = idx / 377, c4 = idx % 377;
        float4 v = make_float4(0.f, 0.f, 0.f, 0.f);
        if (c4 < 375) {
            int lr = 32 + r;
            int grow = (lr / NU) * H_N + u0 + (lr % NU);
            v = *(const float4*)&W_hh[(size_t)grow * H_N + c4 * 4];
        }
        *(float4*)&Wb_s[r * WPAD_B + c4 * 4] = v;
    }
    if (tid < NU) c_s[tid] = 0.f;
    if (tid == 0) uflag[0] = 0u;

    // ---- preload plane-A weights (row = lane, 32 rows) into registers ----
    ulonglong2 wA[NCHUNK];
    {
        int grow = (lane / NU) * H_N + u0 + (lane % NU);
        const float* wrowA = &W_hh[(size_t)grow * H_N];
        #pragma unroll
        for (int k = 0; k < NCHUNK; k++) {
            if (k < NK)
                wA[k] = *(const ulonglong2*)&wrowA[(start + k) * 4];
            else
                wA[k] = make_ulonglong2(0ull, 0ull);
        }
    }

    // plane-B column-split: lanes 0-15 chunks [start,start+12), 16-31 the rest
    const int half   = lane >> 4;
    const int bcnt   = half ? (NK - 12) : 12;
    const float* wbB = &Wb_s[(lane & 15) * WPAD_B + (start + half * 12) * 4];

    // ---- prime cp.async xp ring (steps 0..3) ----
    const uint32_t xr_base = (uint32_t)__cvta_generic_to_shared(xpr);
    const int gate = tid / 3, jj = tid % 3;      // valid for tid<12
    if (tid < 12) {
        #pragma unroll
        for (int tt = 0; tt < 4; tt++) {
            cp_async16(xr_base + (uint32_t)((tt * NROWS + gate * NU + jj * 4) * 4),
                       &g_xp[(size_t)tt * G4 + gate * H_N + u0 + jj * 4]);
            CP_COMMIT();
        }
    }

    __syncthreads();

    for (int t = 0; t < T_STEPS; t++) {
        // loop-top: arrival for step t-1 (fire-and-forget, backpressure only)
        if (tid == 0 && t > 0) red_rel_g(&g_cnt[0]);
        // warp15 lane0: publish backpressure bound (normally instant)
        if (w == 15 && lane == 0) {
            if (t >= 3) {
                unsigned tgt = (unsigned)NCTA * (unsigned)(t - 2);
                while (ld_acq_g(&g_cnt[0]) < tgt) {}
            }
            st_rel_s(bp_addr, (unsigned)t);
        }

        // ---- per-warp readiness: poll only my ~9 producer CTA flags ----
        {
            bool ok;
            do {
                unsigned v = 0xffffffffu;
                if (lane <= c1 - c0) v = ld_acq_g(&g_done[(c0 + lane) * 8]);
                ok = __all_sync(0xffffffffu, v >= (unsigned)t);
            } while (!ok);
        }
        // stage this warp's own h chunk from ring slot t&3
        {
            const float4* hb4 = (const float4*)g_hrep[t & 3][b & (NREP - 1)];
            if (lane < NK) {
                float4 v = __ldcg(&hb4[start + lane]);
                *(float4*)&h_s[(start + lane) * 4] = v;
            }
            __syncwarp();
        }

        // ---- matvec: A-plane (32 rows) + split B-plane ----
        unsigned long long aA0 = 0ull, aA1 = 0ull, aB0 = 0ull, aB1 = 0ull;
        const float* hbase = &h_s[start * 4];
        #pragma unroll
        for (int k = 0; k < NCHUNK; k++) {
            ulonglong2 hv = (k < NK) ? *(const ulonglong2*)&hbase[k * 4]
                                     : make_ulonglong2(0ull, 0ull);
            FMA2(aA0, wA[k].x, hv.x);
            FMA2(aA1, wA[k].y, hv.y);
        }
        const float* hbB = &h_s[(start + half * 12) * 4];
        #pragma unroll
        for (int k = 0; k < 12; k++) {
            bool okk = (k < bcnt);
            ulonglong2 hv = okk ? *(const ulonglong2*)&hbB[k * 4]
                                : make_ulonglong2(0ull, 0ull);
            ulonglong2 wb = okk ? *(const ulonglong2*)&wbB[k * 4]
                                : make_ulonglong2(0ull, 0ull);
            FMA2(aB0, wb.x, hv.x);
            FMA2(aB1, wb.y, hv.y);
        }
        float accA, accB;
        {
            float2 a0 = *(float2*)&aA0, a1 = *(float2*)&aA1;
            accA = (a0.x + a0.y) + (a1.x + a1.y);
            float2 b0 = *(float2*)&aB0, b1 = *(float2*)&aB1;
            accB = (b0.x + b0.y) + (b1.x + b1.y);
        }
        accB += __shfl_xor_sync(0xffffffffu, accB, 16);   // combine column halves
        part[lane * 17 + w] = accA;
        if (lane < NB) part[(32 + lane) * 17 + w] = accB;
        if (w == 0) CP_WAIT3();
        __syncthreads();

        // ---- paired reduce + gates: warp u owns unit u ----
        if (w < NU) {
            const float* xps = &xpr[(t & 3) * NROWS];
            const int rhalf = lane >> 4;
            const int l15   = lane & 15;

            int r01 = w + rhalf * 12;            // i (u) / f (12+u)
            float v01 = part[r01 * 17 + l15];
            v01 += __shfl_xor_sync(0xffffffffu, v01, 8);
            v01 += __shfl_xor_sync(0xffffffffu, v01, 4);
            v01 += __shfl_xor_sync(0xffffffffu, v01, 2);
            v01 += __shfl_xor_sync(0xffffffffu, v01, 1);
            v01 += xps[r01];
            float act01 = sigmoid_f(v01);

            int r23 = 24 + w + rhalf * 12;       // g (24+u) / o (36+u)
            float v23 = part[r23 * 17 + l15];
            v23 += __shfl_xor_sync(0xffffffffu, v23, 8);
            v23 += __shfl_xor_sync(0xffffffffu, v23, 4);
            v23 += __shfl_xor_sync(0xffffffffu, v23, 2);
            v23 += __shfl_xor_sync(0xffffffffu, v23, 1);
            v23 += xps[r23];
            float s = rhalf ? 1.f : 2.f;         // tanh(x)=2*sig(2x)-1
            float act23 = s * __fdividef(1.f, 1.f + __expf(-s * v23)) - (s - 1.f);

            float ig = __shfl_sync(0xffffffffu, act01, 0);
            float fg = __shfl_sync(0xffffffffu, act01, 16);
            float gg = __shfl_sync(0xffffffffu, act23, 0);
            float og = __shfl_sync(0xffffffffu, act23, 16);

            float c = fg * c_s[w] + ig * gg;
            float hval = og * tanh_f(c);
            if (lane == 0) c_s[w] = c;
            // backpressure gate (normally satisfied instantly), then store h(t+1)
            if (lane < NREP) {
                while (ld_acq_s(bp_addr) < (unsigned)t) {}
                g_hrep[(t + 1) & 3][lane][u0 + w] = hval;
            }
        }

        // producers sync; publish done flag; xp(t+4) prefetch
        if (tid < 384)
            asm volatile("bar.sync 1, 384;" ::: "memory");
        if (tid == 0) st_rel_g(&g_done[b * 8], (unsigned)(t + 1));
        if (tid < 12) {
            if (t + 4 < T_STEPS)
                cp_async16(xr_base + (uint32_t)((((t + 4) & 3) * NROWS + gate * NU + jj * 4) * 4),
                           &g_xp[(size_t)(t + 4) * G4 + gate * H_N + u0 + jj * 4]);
            CP_COMMIT();
        }
        __syncthreads();   // WAR on part[] and h_s
    }

    // =================== MLP head ===================
    // stage final h(T) into h_s via the same per-producer flag poll
    {
        bool ok;
        do {
            unsigned v = 0xffffffffu;
            if (lane <= c1 - c0) v = ld_acq_g(&g_done[(c0 + lane) * 8]);
            ok = __all_sync(0xffffffffu, v >= (unsigned)T_STEPS);
        } while (!ok);
        const float4* hb4 = (const float4*)g_hrep[T_STEPS & 3][b & (NREP - 1)];
        if (lane < NK) {
            float4 v = __ldcg(&hb4[start + lane]);
            *(float4*)&h_s[(start + lane) * 4] = v;
        }
    }
    __syncthreads();

    {
        int gw = b * 16 + w;
        if (gw < MLP_HID_N) {
            const float* wr = &W1[(size_t)gw * H_N];
            float acc = 0.f;
            for (int c4 = lane; c4 < 375; c4 += 32) {
                float4 wv = *(const float4*)&wr[c4 * 4];
                float4 h4 = *(const float4*)&h_s[c4 * 4];
                acc += wv.x * h4.x + wv.y * h4.y + wv.z * h4.z + wv.w * h4.w;
            }
            acc += __shfl_xor_sync(0xffffffffu, acc, 16);
            acc += __shfl_xor_sync(0xffffffffu, acc, 8);
            acc += __shfl_xor_sync(0xffffffffu, acc, 4);
            acc += __shfl_xor_sync(0xffffffffu, acc, 2);
            acc += __shfl_xor_sync(0xffffffffu, acc, 1);
            if (lane == 0) g_hid[gw] = acc + b1[gw];
        }
        __syncthreads();
        if (tid == 0) red_rel_g(&g_cnt[64]);

        if (b == 0) {
            if (tid == 0) {
                while (ld_acq_g(&g_cnt[64]) < (unsigned)NCTA) {}
            }
            __syncthreads();
            for (int r = w; r < OUT_N; r += 16) {
                const float* wr = &W2[(size_t)r * MLP_HID_N];
                float acc = 0.f;
                for (int c = lane; c < MLP_HID_N; c += 32)
                    acc += wr[c] * __ldcg(&g_hid[c]);
                acc += __shfl_xor_sync(0xffffffffu, acc, 16);
                acc += __shfl_xor_sync(0xffffffffu, acc, 8);
                acc += __shfl_xor_sync(0xffffffffu, acc, 4);
                acc += __shfl_xor_sync(0xffffffffu, acc, 2);
                acc += __shfl_xor_sync(0xffffffffu, acc, 1);
                if (lane == 0) out[r] = acc + b2[r];
            }
        }
    }
}

// ---------------- launch ----------------
extern "C" void kernel_launch(void* const* d_in, const int* in_sizes, int n_in,
                              void* d_out, int out_size) {
    const float* inp  = (const float*)d_in[0];
    const float* W_ih = (const float*)d_in[1];
    const float* W_hh = (const float*)d_in[2];
    const float* b_ih = (const float*)d_in[3];
    const float* b_hh = (const float*)d_in[4];
    const float* W1   = (const float*)d_in[5];
    const float* b1   = (const float*)d_in[6];
    const float* W2   = (const float*)d_in[7];
    const float* b2   = (const float*)d_in[8];
    float* out = (float*)d_out;

    size_t smem_bytes = (size_t)(NB * WPAD_B + 1504 + NROWS * 17 + 4 * NROWS + 16 + 8)
                        * sizeof(float);
    cudaFuncSetAttribute(lstm_kernel, cudaFuncAttributeMaxDynamicSharedMemorySize,
                         (int)smem_bytes);

    pre_kernel<<<dim3(24, 32), 256>>>(inp, W_ih, b_ih, b_hh);
    lstm_kernel<<<NCTA, NTHREADS, smem_bytes>>>(W_hh, W1, b1, W2, b2, out);
}

// round 12
// speedup vs baseline: 1.1605x; 1.1605x over previous
#include <cuda_runtime.h>
#include <cstdint>

#define H_N      1500
#define G4       6000
#define T_STEPS  4096
#define MLP_HID_N 1875
#define OUT_N    20
#define IN_N     20
#define NCTA     125         // 125 CTAs x 12 units = 1500
#define NLO      63          // CTAs 0..62 produce h[0:756)
#define NHI      62          // CTAs 63..124 produce h[756:1500)
#define NTHREADS 512
#define NU       12
#define NROWS    48
#define NB       16          // plane-B rows (smem)
#define NREP     4           // h replication factor
#define WPAD_B   1508
#define NCHUNK   24          // 375 = 7*24 + 9*23

// ---------------- device scratch ----------------
__device__ float    g_xp[(size_t)T_STEPS * G4];
__device__ float    g_hrep[2][NREP][1504];
__device__ float    g_hid[MLP_HID_N];
__device__ unsigned g_cnt[192];   // [0]=lo, [64]=hi, [128]=mlp

#define FMA2(acc, a, b) \
    asm("fma.rn.f32x2 %0, %1, %2, %0;" : "+l"(acc) : "l"(a), "l"(b))

__device__ __forceinline__ float tanh_f(float x) {
    return __fdividef(2.f, 1.f + __expf(-2.f * x)) - 1.f;
}

__device__ __forceinline__ void cp_async16(uint32_t dst, const float* src) {
    asm volatile("cp.async.cg.shared.global [%0], [%1], 16;" :: "r"(dst), "l"(src));
}
#define CP_COMMIT() asm volatile("cp.async.commit_group;" ::: "memory")
#define CP_WAIT3()  asm volatile("cp.async.wait_group 3;" ::: "memory")

__device__ __forceinline__ unsigned ld_acq_g(const unsigned* p) {
    unsigned v;
    asm volatile("ld.acquire.gpu.global.u32 %0, [%1];" : "=r"(v) : "l"(p) : "memory");
    return v;
}
__device__ __forceinline__ void red_rel_g(unsigned* p) {
    asm volatile("red.release.gpu.global.add.u32 [%0], 1;" :: "l"(p) : "memory");
}
__device__ __forceinline__ void st_rel_s(uint32_t a, unsigned v) {
    asm volatile("st.release.cta.shared.u32 [%0], %1;" :: "r"(a), "r"(v) : "memory");
}
__device__ __forceinline__ unsigned ld_acq_s(uint32_t a) {
    unsigned v;
    asm volatile("ld.acquire.cta.shared.u32 %0, [%1];" : "=r"(v) : "r"(a) : "memory");
    return v;
}

// ---------------- pre: init state + x_proj ----------------
__global__ void pre_kernel(const float* __restrict__ inp,
                           const float* __restrict__ W_ih,
                           const float* __restrict__ b_ih,
                           const float* __restrict__ b_hh) {
    __shared__ float Wsm[256 * 21];
    __shared__ float bsm[256];
    __shared__ float insm[128 * IN_N];
    int tid = threadIdx.x;
    int r0 = blockIdx.x * 256;
    int t0 = blockIdx.y * 128;

    if (blockIdx.x == 0 && blockIdx.y == 0) {
        float* hz = &g_hrep[0][0][0];
        for (int i = tid; i < 2 * NREP * 1504; i += 256) hz[i] = 0.f;
        for (int i = tid; i < 192; i += 256) g_cnt[i] = 0u;
    }

    for (int i = tid; i < 256 * IN_N; i += 256) {
        int rr = i / IN_N, k = i % IN_N;
        int row = r0 + rr;
        Wsm[rr * 21 + k] = (row < G4) ? W_ih[row * IN_N + k] : 0.f;
    }
    {
        int row = r0 + tid;
        bsm[tid] = (row < G4) ? (b_ih[row] + b_hh[row]) : 0.f;
    }
    for (int i = tid; i < 128 * IN_N; i += 256)
        insm[i] = inp[t0 * IN_N + i];
    __syncthreads();

    int row = r0 + tid;
    if (row < G4) {
        const float* wrow = &Wsm[tid * 21];
        float bias = bsm[tid];
        for (int tt = 0; tt < 128; tt++) {
            const float* ir = &insm[tt * IN_N];
            float acc = bias;
            #pragma unroll
            for (int k = 0; k < IN_N; k++) acc += ir[k] * wrow[k];
            g_xp[(size_t)(t0 + tt) * G4 + row] = acc;
        }
    }
}

// ---------------- persistent LSTM + MLP ----------------
__global__ void __launch_bounds__(NTHREADS, 1)
lstm_kernel(const float* __restrict__ W_hh,
            const float* __restrict__ W1,
            const float* __restrict__ b1,
            const float* __restrict__ W2,
            const float* __restrict__ b2,
            float* __restrict__ out) {
    extern __shared__ float smem[];
    float* Wb_s  = smem;                         // NB * WPAD_B = 24128
    float* h_s   = Wb_s + NB * WPAD_B;           // 2 * 1504 (ping-pong)
    float* part  = h_s + 2 * 1504;               // 2 * 816 (ping-pong)
    float* xpr   = part + 2 * 816;               // 4 * 48
    float* c_s   = xpr + 4 * NROWS;              // 16
    unsigned* uflag = (unsigned*)(c_s + 16);     // [0]=lo flag, [1]=hi flag

    const int tid  = threadIdx.x;
    const int lane = tid & 31;
    const int w    = tid >> 5;
    const int b    = blockIdx.x;
    const int u0   = b * NU;

    const int NK    = (w < 7) ? 24 : 23;
    const int start = (w < 7) ? w * 24 : 168 + (w - 7) * 23;

    // column-range needs: lo half = floats [0,756), hi = [756,1500)
    const bool need_lo = (start * 4) < 756;
    const bool need_hi = (start * 4 + NK * 4) > 756;

    const uint32_t fl_lo = (uint32_t)__cvta_generic_to_shared(uflag);
    const uint32_t fl_hi = fl_lo + 4;

    // ---- preload plane-B weights (rows 32..47) into smem ----
    for (int idx = tid; idx < NB * 377; idx += NTHREADS) {
        int r = idx / 377, c4 = idx % 377;
        float4 v = make_float4(0.f, 0.f, 0.f, 0.f);
        if (c4 < 375) {
            int lr = 32 + r;
            int grow = (lr / NU) * H_N + u0 + (lr % NU);
            v = *(const float4*)&W_hh[(size_t)grow * H_N + c4 * 4];
        }
        *(float4*)&Wb_s[r * WPAD_B + c4 * 4] = v;
    }
    if (tid < NU) c_s[tid] = 0.f;
    if (tid < 2) uflag[tid] = 0u;

    // ---- preload plane-A weights (row = lane, 32 rows) into registers ----
    ulonglong2 wA[NCHUNK];
    {
        int grow = (lane / NU) * H_N + u0 + (lane % NU);
        const float* wrowA = &W_hh[(size_t)grow * H_N];
        #pragma unroll
        for (int k = 0; k < NCHUNK; k++) {
            if (k < NK)
                wA[k] = *(const ulonglong2*)&wrowA[(start + k) * 4];
            else
                wA[k] = make_ulonglong2(0ull, 0ull);
        }
    }

    // plane-B column-split: lanes 0-15 chunks [start,start+12), 16-31 the rest
    const int half   = lane >> 4;
    const int bcnt   = half ? (NK - 12) : 12;
    const float* wbB = &Wb_s[(lane & 15) * WPAD_B + (start + half * 12) * 4];

    // ---- prime cp.async xp ring (steps 0..3) ----
    const uint32_t xr_base = (uint32_t)__cvta_generic_to_shared(xpr);
    const int gate = tid / 3, jj = tid % 3;      // valid for tid<12
    if (tid < 12) {
        #pragma unroll
        for (int tt = 0; tt < 4; tt++) {
            cp_async16(xr_base + (uint32_t)((tt * NROWS + gate * NU + jj * 4) * 4),
                       &g_xp[(size_t)tt * G4 + gate * H_N + u0 + jj * 4]);
            CP_COMMIT();
        }
    }

    __syncthreads();

    for (int t = 0; t < T_STEPS; t++) {
        const unsigned tp1 = (unsigned)(t + 1);

        // free warps 12/13 poll the group counters and publish smem flags
        if (w == 12 && lane == 0) {
            while (ld_acq_g(&g_cnt[64]) < (unsigned)NHI * (unsigned)t) {}
            st_rel_s(fl_hi, tp1);
        }
        if (w == 13 && lane == 0) {
            while (ld_acq_g(&g_cnt[0]) < (unsigned)NLO * (unsigned)t) {}
            st_rel_s(fl_lo, tp1);
        }
        // every warp spins only the cheap CTA-local flags it needs
        if (need_lo) { while (ld_acq_s(fl_lo) < tp1) {} }
        if (need_hi) { while (ld_acq_s(fl_hi) < tp1) {} }

        // stage this warp's own h chunk (ping-pong smem buffer)
        float* hs = h_s + (t & 1) * 1504;
        {
            const float4* hb4 = (const float4*)g_hrep[t & 1][b & (NREP - 1)];
            if (lane < NK) {
                float4 v = __ldcg(&hb4[start + lane]);
                *(float4*)&hs[(start + lane) * 4] = v;
            }
            __syncwarp();
        }

        // ---- matvec: A-plane (32 rows) + split B-plane ----
        unsigned long long aA0 = 0ull, aA1 = 0ull, aB0 = 0ull, aB1 = 0ull;
        const float* hbase = &hs[start * 4];
        #pragma unroll
        for (int k = 0; k < NCHUNK; k++) {
            ulonglong2 hv = (k < NK) ? *(const ulonglong2*)&hbase[k * 4]
                                     : make_ulonglong2(0ull, 0ull);
            FMA2(aA0, wA[k].x, hv.x);
            FMA2(aA1, wA[k].y, hv.y);
        }
        const float* hbB = &hs[(start + half * 12) * 4];
        #pragma unroll
        for (int k = 0; k < 12; k++) {
            bool okk = (k < bcnt);
            ulonglong2 hv = okk ? *(const ulonglong2*)&hbB[k * 4]
                                : make_ulonglong2(0ull, 0ull);
            ulonglong2 wb = okk ? *(const ulonglong2*)&wbB[k * 4]
                                : make_ulonglong2(0ull, 0ull);
            FMA2(aB0, wb.x, hv.x);
            FMA2(aB1, wb.y, hv.y);
        }
        float accA, accB;
        {
            float2 a0 = *(float2*)&aA0, a1 = *(float2*)&aA1;
            accA = (a0.x + a0.y) + (a1.x + a1.y);
            float2 b0 = *(float2*)&aB0, b1 = *(float2*)&aB1;
            accB = (b0.x + b0.y) + (b1.x + b1.y);
        }
        accB += __shfl_xor_sync(0xffffffffu, accB, 16);   // combine column halves
        float* pw = part + (t & 1) * 816;
        pw[lane * 17 + w] = accA;
        if (lane < NB) pw[(32 + lane) * 17 + w] = accB;

        if (w < 12) {
            if (w == 0) CP_WAIT3();
            asm volatile("bar.sync 2, 512;" ::: "memory");   // wait all 16 warps' parts

            // ---- one-round reduce + gates: 4 gates x 8 lanes in parallel ----
            const float* pr  = part + (t & 1) * 816;
            const float* xps = &xpr[(t & 3) * NROWS];
            const int gidx = lane >> 3;          // 0:i 1:f 2:g 3:o
            const int sub  = lane & 7;
            const int row  = gidx * 12 + w;
            float v = pr[row * 17 + sub] + pr[row * 17 + 8 + sub];
            v += __shfl_xor_sync(0xffffffffu, v, 4);
            v += __shfl_xor_sync(0xffffffffu, v, 2);
            v += __shfl_xor_sync(0xffffffffu, v, 1);
            v += xps[row];
            float s = (gidx == 2) ? 2.f : 1.f;   // tanh(x) = 2*sig(2x)-1
            float act = s * __fdividef(1.f, 1.f + __expf(-s * v)) - (s - 1.f);
            float ig = __shfl_sync(0xffffffffu, act, 0);
            float fg = __shfl_sync(0xffffffffu, act, 8);
            float gg = __shfl_sync(0xffffffffu, act, 16);
            float og = __shfl_sync(0xffffffffu, act, 24);
            float c = fg * c_s[w] + ig * gg;
            float hval = og * tanh_f(c);
            if (lane == 0) c_s[w] = c;
            if (lane < NREP)
                g_hrep[(t + 1) & 1][lane][u0 + w] = hval;

            asm volatile("bar.sync 1, 384;" ::: "memory");   // 12 unit warps
            if (tid == 0) red_rel_g((b < NLO) ? &g_cnt[0] : &g_cnt[64]);
            if (tid < 12) {
                if (t + 4 < T_STEPS)
                    cp_async16(xr_base + (uint32_t)((((t + 4) & 3) * NROWS + gate * NU + jj * 4) * 4),
                               &g_xp[(size_t)(t + 4) * G4 + gate * H_N + u0 + jj * 4]);
                CP_COMMIT();
            }
        } else {
            asm volatile("bar.arrive 2, 512;" ::: "memory"); // non-blocking; free-run
        }
    }

    // wait for ALL CTAs' final h before the MLP reads it
    if (tid == 0) {
        while (ld_acq_g(&g_cnt[0])  < (unsigned)NLO * (unsigned)T_STEPS) {}
        while (ld_acq_g(&g_cnt[64]) < (unsigned)NHI * (unsigned)T_STEPS) {}
    }
    __syncthreads();

    // =================== MLP head (final h in g_hrep[0][*]) ===================
    {
        int gw = b * 16 + w;
        if (gw < MLP_HID_N) {
            const float* wr = &W1[(size_t)gw * H_N];
            const float* hv = g_hrep[0][b & (NREP - 1)];
            float acc = 0.f;
            for (int c4 = lane; c4 < 375; c4 += 32) {
                float4 wv = *(const float4*)&wr[c4 * 4];
                float4 h4 = __ldcg((const float4*)&hv[c4 * 4]);
                acc += wv.x * h4.x + wv.y * h4.y + wv.z * h4.z + wv.w * h4.w;
            }
            acc += __shfl_xor_sync(0xffffffffu, acc, 16);
            acc += __shfl_xor_sync(0xffffffffu, acc, 8);
            acc += __shfl_xor_sync(0xffffffffu, acc, 4);
            acc += __shfl_xor_sync(0xffffffffu, acc, 2);
            acc += __shfl_xor_sync(0xffffffffu, acc, 1);
            if (lane == 0) g_hid[gw] = acc + b1[gw];
        }
        __syncthreads();
        if (tid == 0) red_rel_g(&g_cnt[128]);

        if (b == 0) {
            if (tid == 0) {
                while (ld_acq_g(&g_cnt[128]) < (unsigned)NCTA) {}
            }
            __syncthreads();
            for (int r = w; r < OUT_N; r += 16) {
                const float* wr = &W2[(size_t)r * MLP_HID_N];
                float acc = 0.f;
                for (int c = lane; c < MLP_HID_N; c += 32)
                    acc += wr[c] * __ldcg(&g_hid[c]);
                acc += __shfl_xor_sync(0xffffffffu, acc, 16);
                acc += __shfl_xor_sync(0xffffffffu, acc, 8);
                acc += __shfl_xor_sync(0xffffffffu, acc, 4);
                acc += __shfl_xor_sync(0xffffffffu, acc, 2);
                acc += __shfl_xor_sync(0xffffffffu, acc, 1);
                if (lane == 0) out[r] = acc + b2[r];
            }
        }
    }
}

// ---------------- launch ----------------
extern "C" void kernel_launch(void* const* d_in, const int* in_sizes, int n_in,
                              void* d_out, int out_size) {
    const float* inp  = (const float*)d_in[0];
    const float* W_ih = (const float*)d_in[1];
    const float* W_hh = (const float*)d_in[2];
    const float* b_ih = (const float*)d_in[3];
    const float* b_hh = (const float*)d_in[4];
    const float* W1   = (const float*)d_in[5];
    const float* b1   = (const float*)d_in[6];
    const float* W2   = (const float*)d_in[7];
    const float* b2   = (const float*)d_in[8];
    float* out = (float*)d_out;

    size_t smem_bytes = (size_t)(NB * WPAD_B + 2 * 1504 + 2 * 816 + 4 * NROWS + 16 + 8)
                        * sizeof(float);
    cudaFuncSetAttribute(lstm_kernel, cudaFuncAttributeMaxDynamicSharedMemorySize,
                         (int)smem_bytes);

    pre_kernel<<<dim3(24, 32), 256>>>(inp, W_ih, b_ih, b_hh);
    lstm_kernel<<<NCTA, NTHREADS, smem_bytes>>>(W_hh, W1, b1, W2, b2, out);
}

// round 14
// speedup vs baseline: 1.2635x; 1.0888x over previous
#include <cuda_runtime.h>
#include <cstdint>

#define H_N      1500
#define G4       6000
#define T_STEPS  4096
#define MLP_HID_N 1875
#define OUT_N    20
#define IN_N     20
#define NCTA     125         // 125 CTAs x 12 units = 1500
#define NTHREADS 512
#define NU       12
#define NROWS    48
#define NB       16          // plane-B rows (smem)
#define NREP     4           // h replication factor
#define DEPTH    4           // LL ring depth
#define WPAD_B   1508
#define NCHUNK   24          // 375 = 7*24 + 9*23

// ---------------- device scratch ----------------
__device__ float    g_xp[(size_t)T_STEPS * G4];
__device__ uint2    g_hx[DEPTH][NREP][1504];   // LL pairs: (h bits, step tag)
__device__ float    g_hid[MLP_HID_N];
__device__ unsigned g_cnt[128];                // [0]=backpressure, [64]=mlp

#define FMA2(acc, a, b) \
    asm("fma.rn.f32x2 %0, %1, %2, %0;" : "+l"(acc) : "l"(a), "l"(b))

__device__ __forceinline__ float tanh_f(float x) {
    return __fdividef(2.f, 1.f + __expf(-2.f * x)) - 1.f;
}

__device__ __forceinline__ void cp_async16(uint32_t dst, const float* src) {
    asm volatile("cp.async.cg.shared.global [%0], [%1], 16;" :: "r"(dst), "l"(src));
}
#define CP_COMMIT() asm volatile("cp.async.commit_group;" ::: "memory")
#define CP_WAIT3()  asm volatile("cp.async.wait_group 3;" ::: "memory")

__device__ __forceinline__ unsigned ld_acq_g(const unsigned* p) {
    unsigned v;
    asm volatile("ld.acquire.gpu.global.u32 %0, [%1];" : "=r"(v) : "l"(p) : "memory");
    return v;
}
__device__ __forceinline__ void red_rel_g(unsigned* p) {
    asm volatile("red.release.gpu.global.add.u32 [%0], 1;" :: "l"(p) : "memory");
}
__device__ __forceinline__ void st_rel_s(uint32_t a, unsigned v) {
    asm volatile("st.release.cta.shared.u32 [%0], %1;" :: "r"(a), "r"(v) : "memory");
}
__device__ __forceinline__ unsigned ld_acq_s(uint32_t a) {
    unsigned v;
    asm volatile("ld.acquire.cta.shared.u32 %0, [%1];" : "=r"(v) : "r"(a) : "memory");
    return v;
}
__device__ __forceinline__ uint2 ll_ld(const uint2* p) {
    uint2 v;
    asm volatile("ld.volatile.global.v2.u32 {%0,%1}, [%2];"
                 : "=r"(v.x), "=r"(v.y) : "l"(p) : "memory");
    return v;
}
__device__ __forceinline__ void ll_st(uint2* p, unsigned d, unsigned tag) {
    asm volatile("st.volatile.global.v2.u32 [%0], {%1,%2};"
                 :: "l"(p), "r"(d), "r"(tag) : "memory");
}

// ---------------- pre: init state + x_proj ----------------
__global__ void pre_kernel(const float* __restrict__ inp,
                           const float* __restrict__ W_ih,
                           const float* __restrict__ b_ih,
                           const float* __restrict__ b_hh) {
    __shared__ float Wsm[256 * 21];
    __shared__ float bsm[256];
    __shared__ float insm[128 * IN_N];
    int tid = threadIdx.x;
    int r0 = blockIdx.x * 256;
    int t0 = blockIdx.y * 128;

    if (blockIdx.x == 0 && blockIdx.y == 0) {
        uint2* hx = &g_hx[0][0][0];
        for (int i = tid; i < DEPTH * NREP * 1504; i += 256)
            hx[i] = make_uint2(0u, 0u);          // h(0)=0, tag 0
        for (int i = tid; i < 128; i += 256) g_cnt[i] = 0u;
    }

    for (int i = tid; i < 256 * IN_N; i += 256) {
        int rr = i / IN_N, k = i % IN_N;
        int row = r0 + rr;
        Wsm[rr * 21 + k] = (row < G4) ? W_ih[row * IN_N + k] : 0.f;
    }
    {
        int row = r0 + tid;
        bsm[tid] = (row < G4) ? (b_ih[row] + b_hh[row]) : 0.f;
    }
    for (int i = tid; i < 128 * IN_N; i += 256)
        insm[i] = inp[t0 * IN_N + i];
    __syncthreads();

    int row = r0 + tid;
    if (row < G4) {
        const float* wrow = &Wsm[tid * 21];
        float bias = bsm[tid];
        for (int tt = 0; tt < 128; tt++) {
            const float* ir = &insm[tt * IN_N];
            float acc = bias;
            #pragma unroll
            for (int k = 0; k < IN_N; k++) acc += ir[k] * wrow[k];
            g_xp[(size_t)(t0 + tt) * G4 + row] = acc;
        }
    }
}

// ---------------- persistent LSTM + MLP ----------------
__global__ void __launch_bounds__(NTHREADS, 1)
lstm_kernel(const float* __restrict__ W_hh,
            const float* __restrict__ W1,
            const float* __restrict__ b1,
            const float* __restrict__ W2,
            const float* __restrict__ b2,
            float* __restrict__ out) {
    extern __shared__ float smem[];
    float* Wb_s  = smem;                         // NB * WPAD_B
    float* h_s   = Wb_s + NB * WPAD_B;           // 2 * 1504 (warp-private regions)
    float* part  = h_s + 2 * 1504;               // 4 * 816 (4-deep ping-pong)
    float* xpr   = part + 4 * 816;               // 4 * 48
    float* c_s   = xpr + 4 * NROWS;              // 16
    unsigned* uflag = (unsigned*)(c_s + 16);     // [0] = backpressure bound

    const int tid  = threadIdx.x;
    const int lane = tid & 31;
    const int w    = tid >> 5;
    const int b    = blockIdx.x;
    const int u0   = b * NU;

    const int NK    = (w < 7) ? 24 : 23;
    const int start = (w < 7) ? w * 24 : 168 + (w - 7) * 23;
    const int ubase = start * 4;                 // first unit index of my columns
    const int ucnt  = NK * 4;                    // 92 or 96 units

    const uint32_t bp_addr = (uint32_t)__cvta_generic_to_shared(uflag);

    // ---- preload plane-B weights (rows 32..47) into smem ----
    for (int idx = tid; idx < NB * 377; idx += NTHREADS) {
        int r = idx / 377, c4 = idx % 377;
        float4 v = make_float4(0.f, 0.f, 0.f, 0.f);
        if (c4 < 375) {
            int lr = 32 + r;
            int grow = (lr / NU) * H_N + u0 + (lr % NU);
            v = *(const float4*)&W_hh[(size_t)grow * H_N + c4 * 4];
        }
        *(float4*)&Wb_s[r * WPAD_B + c4 * 4] = v;
    }
    if (tid < NU) c_s[tid] = 0.f;
    if (tid == 0) uflag[0] = 0u;

    // ---- preload plane-A weights (row = lane, 32 rows) into registers ----
    ulonglong2 wA[NCHUNK];
    {
        int grow = (lane / NU) * H_N + u0 + (lane % NU);
        const float* wrowA = &W_hh[(size_t)grow * H_N];
        #pragma unroll
        for (int k = 0; k < NCHUNK; k++) {
            if (k < NK)
                wA[k] = *(const ulonglong2*)&wrowA[(start + k) * 4];
            else
                wA[k] = make_ulonglong2(0ull, 0ull);
        }
    }

    // plane-B column-split: lanes 0-15 chunks [start,start+12), 16-31 the rest
    const int half   = lane >> 4;
    const int bcnt   = half ? (NK - 12) : 12;
    const float* wbB = &Wb_s[(lane & 15) * WPAD_B + (start + half * 12) * 4];

    // ---- prime cp.async xp ring (steps 0..3) ----
    const uint32_t xr_base = (uint32_t)__cvta_generic_to_shared(xpr);
    const int gate = tid / 3, jj = tid % 3;      // valid for tid<12
    if (tid < 12) {
        #pragma unroll
        for (int tt = 0; tt < 4; tt++) {
            cp_async16(xr_base + (uint32_t)((tt * NROWS + gate * NU + jj * 4) * 4),
                       &g_xp[(size_t)tt * G4 + gate * H_N + u0 + jj * 4]);
            CP_COMMIT();
        }
    }

    __syncthreads();

    for (int t = 0; t < T_STEPS; t++) {
        // warp15 lane0: lazy ring backpressure bound (normally instant)
        if (w == 15 && lane == 0) {
            if (t >= 3) {
                unsigned tgt = (unsigned)NCTA * (unsigned)(t - 2);
                while (ld_acq_g(&g_cnt[0]) < tgt) {}
            }
            st_rel_s(bp_addr, (unsigned)t);
        }

        // ---- LL poll+stage: fused discovery + data transfer ----
        float* hs = h_s + (t & 1) * 1504;
        {
            const uint2* hb = g_hx[t & 3][b & (NREP - 1)];
            const unsigned tagv = (unsigned)t;
            unsigned needm = 1u;
            if (lane + 32 < ucnt) needm |= 2u;
            if (lane + 64 < ucnt) needm |= 4u;
            do {
                if (needm & 1u) {
                    uint2 p = ll_ld(&hb[ubase + lane]);
                    if (p.y == tagv) { hs[ubase + lane] = __uint_as_float(p.x); needm &= ~1u; }
                }
                if (needm & 2u) {
                    uint2 p = ll_ld(&hb[ubase + lane + 32]);
                    if (p.y == tagv) { hs[ubase + lane + 32] = __uint_as_float(p.x); needm &= ~2u; }
                }
                if (needm & 4u) {
                    uint2 p = ll_ld(&hb[ubase + lane + 64]);
                    if (p.y == tagv) { hs[ubase + lane + 64] = __uint_as_float(p.x); needm &= ~4u; }
                }
            } while (!__all_sync(0xffffffffu, needm == 0u));
            __syncwarp();
        }

        // ---- matvec: A-plane (32 rows) + split B-plane ----
        unsigned long long aA0 = 0ull, aA1 = 0ull, aB0 = 0ull, aB1 = 0ull;
        const float* hbase = &hs[start * 4];
        #pragma unroll
        for (int k = 0; k < NCHUNK; k++) {
            ulonglong2 hv = (k < NK) ? *(const ulonglong2*)&hbase[k * 4]
                                     : make_ulonglong2(0ull, 0ull);
            FMA2(aA0, wA[k].x, hv.x);
            FMA2(aA1, wA[k].y, hv.y);
        }
        const float* hbB = &hs[(start + half * 12) * 4];
        #pragma unroll
        for (int k = 0; k < 12; k++) {
            bool okk = (k < bcnt);
            ulonglong2 hv = okk ? *(const ulonglong2*)&hbB[k * 4]
                                : make_ulonglong2(0ull, 0ull);
            ulonglong2 wb = okk ? *(const ulonglong2*)&wbB[k * 4]
                                : make_ulonglong2(0ull, 0ull);
            FMA2(aB0, wb.x, hv.x);
            FMA2(aB1, wb.y, hv.y);
        }
        float accA, accB;
        {
            float2 a0 = *(float2*)&aA0, a1 = *(float2*)&aA1;
            accA = (a0.x + a0.y) + (a1.x + a1.y);
            float2 b0 = *(float2*)&aB0, b1 = *(float2*)&aB1;
            accB = (b0.x + b0.y) + (b1.x + b1.y);
        }
        accB += __shfl_xor_sync(0xffffffffu, accB, 16);   // combine column halves
        float* pw = part + (t & 3) * 816;
        pw[lane * 17 + w] = accA;
        if (lane < NB) pw[(32 + lane) * 17 + w] = accB;

        if (w == 0) CP_WAIT3();
        __syncthreads();   // ALL warps: consumption of slot t provably done here

        if (w < 12) {
            // ---- one-round reduce + gates: 4 gates x 8 lanes in parallel ----
            const float* pr  = part + (t & 3) * 816;
            const float* xps = &xpr[(t & 3) * NROWS];
            const int gidx = lane >> 3;          // 0:i 1:f 2:g 3:o
            const int sub  = lane & 7;
            const int row  = gidx * 12 + w;
            float v = pr[row * 17 + sub] + pr[row * 17 + 8 + sub];
            v += __shfl_xor_sync(0xffffffffu, v, 4);
            v += __shfl_xor_sync(0xffffffffu, v, 2);
            v += __shfl_xor_sync(0xffffffffu, v, 1);
            v += xps[row];
            float s = (gidx == 2) ? 2.f : 1.f;   // tanh(x) = 2*sig(2x)-1
            float act = s * __fdividef(1.f, 1.f + __expf(-s * v)) - (s - 1.f);
            float ig = __shfl_sync(0xffffffffu, act, 0);
            float fg = __shfl_sync(0xffffffffu, act, 8);
            float gg = __shfl_sync(0xffffffffu, act, 16);
            float og = __shfl_sync(0xffffffffu, act, 24);
            float c = fg * c_s[w] + ig * gg;
            float hval = og * tanh_f(c);
            if (lane == 0) c_s[w] = c;
            // LL store h(t+1) to all replicas (tag = t+1), after backpressure gate
            if (lane < NREP) {
                while (ld_acq_s(bp_addr) < (unsigned)t) {}
                ll_st(&g_hx[(t + 1) & 3][lane][u0 + w],
                      __float_as_uint(hval), (unsigned)(t + 1));
            }

            asm volatile("bar.sync 1, 384;" ::: "memory");   // 12 unit warps
            if (tid == 0) red_rel_g(&g_cnt[0]);              // step-complete arrival
            if (tid < 12) {
                if (t + 4 < T_STEPS)
                    cp_async16(xr_base + (uint32_t)((((t + 4) & 3) * NROWS + gate * NU + jj * 4) * 4),
                               &g_xp[(size_t)(t + 4) * G4 + gate * H_N + u0 + jj * 4]);
                CP_COMMIT();
            }
        }
        // warps 12-15 free-run into the next step's LL poll
    }

    // =================== MLP head ===================
    // stage final h(T) into h_s[0] via the same LL tag-poll
    {
        float* hs = h_s;
        const uint2* hb = g_hx[T_STEPS & 3][b & (NREP - 1)];
        const unsigned tagv = (unsigned)T_STEPS;
        unsigned needm = 1u;
        if (lane + 32 < ucnt) needm |= 2u;
        if (lane + 64 < ucnt) needm |= 4u;
        do {
            if (needm & 1u) {
                uint2 p = ll_ld(&hb[ubase + lane]);
                if (p.y == tagv) { hs[ubase + lane] = __uint_as_float(p.x); needm &= ~1u; }
            }
            if (needm & 2u) {
                uint2 p = ll_ld(&hb[ubase + lane + 32]);
                if (p.y == tagv) { hs[ubase + lane + 32] = __uint_as_float(p.x); needm &= ~2u; }
            }
            if (needm & 4u) {
                uint2 p = ll_ld(&hb[ubase + lane + 64]);
                if (p.y == tagv) { hs[ubase + lane + 64] = __uint_as_float(p.x); needm &= ~4u; }
            }
        } while (!__all_sync(0xffffffffu, needm == 0u));
    }
    __syncthreads();

    {
        int gw = b * 16 + w;
        if (gw < MLP_HID_N) {
            const float* wr = &W1[(size_t)gw * H_N];
            float acc = 0.f;
            for (int c4 = lane; c4 < 375; c4 += 32) {
                float4 wv = *(const float4*)&wr[c4 * 4];
                float4 h4 = *(const float4*)&h_s[c4 * 4];
                acc += wv.x * h4.x + wv.y * h4.y + wv.z * h4.z + wv.w * h4.w;
            }
            acc += __shfl_xor_sync(0xffffffffu, acc, 16);
            acc += __shfl_xor_sync(0xffffffffu, acc, 8);
            acc += __shfl_xor_sync(0xffffffffu, acc, 4);
            acc += __shfl_xor_sync(0xffffffffu, acc, 2);
            acc += __shfl_xor_sync(0xffffffffu, acc, 1);
            if (lane == 0) g_hid[gw] = acc + b1[gw];
        }
        __syncthreads();
        if (tid == 0) red_rel_g(&g_cnt[64]);

        if (b == 0) {
            if (tid == 0) {
                while (ld_acq_g(&g_cnt[64]) < (unsigned)NCTA) {}
            }
            __syncthreads();
            for (int r = w; r < OUT_N; r += 16) {
                const float* wr = &W2[(size_t)r * MLP_HID_N];
                float acc = 0.f;
                for (int c = lane; c < MLP_HID_N; c += 32)
                    acc += wr[c] * __ldcg(&g_hid[c]);
                acc += __shfl_xor_sync(0xffffffffu, acc, 16);
                acc += __shfl_xor_sync(0xffffffffu, acc, 8);
                acc += __shfl_xor_sync(0xffffffffu, acc, 4);
                acc += __shfl_xor_sync(0xffffffffu, acc, 2);
                acc += __shfl_xor_sync(0xffffffffu, acc, 1);
                if (lane == 0) out[r] = acc + b2[r];
            }
        }
    }
}

// ---------------- launch ----------------
extern "C" void kernel_launch(void* const* d_in, const int* in_sizes, int n_in,
                              void* d_out, int out_size) {
    const float* inp  = (const float*)d_in[0];
    const float* W_ih = (const float*)d_in[1];
    const float* W_hh = (const float*)d_in[2];
    const float* b_ih = (const float*)d_in[3];
    const float* b_hh = (const float*)d_in[4];
    const float* W1   = (const float*)d_in[5];
    const float* b1   = (const float*)d_in[6];
    const float* W2   = (const float*)d_in[7];
    const float* b2   = (const float*)d_in[8];
    float* out = (float*)d_out;

    size_t smem_bytes = (size_t)(NB * WPAD_B + 2 * 1504 + 4 * 816 + 4 * NROWS + 16 + 8)
                        * sizeof(float);
    cudaFuncSetAttribute(lstm_kernel, cudaFuncAttributeMaxDynamicSharedMemorySize,
                         (int)smem_bytes);

    pre_kernel<<<dim3(24, 32), 256>>>(inp, W_ih, b_ih, b_hh);
    lstm_kernel<<<NCTA, NTHREADS, smem_bytes>>>(W_hh, W1, b1, W2, b2, out);
}

// round 15
// speedup vs baseline: 1.5004x; 1.1875x over previous
#include <cuda_runtime.h>
#include <cstdint>

#define H_N      1500
#define G4       6000
#define T_STEPS  4096
#define MLP_HID_N 1875
#define OUT_N    20
#define IN_N     20
#define NCTA     125         // 125 CTAs x 12 units = 1500
#define NTHREADS 512
#define NU       12
#define NROWS    48
#define NB       16          // plane-B rows (smem)
#define NREP     4           // h replication factor
#define DEPTH    4           // LL ring depth
#define NGRP     500         // 1500 units / 3 per LL128 pair
#define GPAD     504
#define WPAD_B   1508
#define NCHUNK   24          // 375 = 7*24 + 9*23

// ---------------- device scratch ----------------
__device__ float    g_xp[(size_t)T_STEPS * G4];
__device__ uint4    g_hx4[DEPTH][NREP][GPAD];  // LL128 pairs: {h0,h1,h2,tag}
__device__ float    g_hid[MLP_HID_N];
__device__ unsigned g_cnt[128];                // [0]=backpressure, [64]=mlp

#define FMA2(acc, a, b) \
    asm("fma.rn.f32x2 %0, %1, %2, %0;" : "+l"(acc) : "l"(a), "l"(b))

__device__ __forceinline__ float tanh_f(float x) {
    return __fdividef(2.f, 1.f + __expf(-2.f * x)) - 1.f;
}

__device__ __forceinline__ void cp_async16(uint32_t dst, const float* src) {
    asm volatile("cp.async.cg.shared.global [%0], [%1], 16;" :: "r"(dst), "l"(src));
}
#define CP_COMMIT() asm volatile("cp.async.commit_group;" ::: "memory")
#define CP_WAIT3()  asm volatile("cp.async.wait_group 3;" ::: "memory")

__device__ __forceinline__ unsigned ld_acq_g(const unsigned* p) {
    unsigned v;
    asm volatile("ld.acquire.gpu.global.u32 %0, [%1];" : "=r"(v) : "l"(p) : "memory");
    return v;
}
__device__ __forceinline__ void red_rel_g(unsigned* p) {
    asm volatile("red.release.gpu.global.add.u32 [%0], 1;" :: "l"(p) : "memory");
}
__device__ __forceinline__ void st_rel_s(uint32_t a, unsigned v) {
    asm volatile("st.release.cta.shared.u32 [%0], %1;" :: "r"(a), "r"(v) : "memory");
}
__device__ __forceinline__ unsigned ld_acq_s(uint32_t a) {
    unsigned v;
    asm volatile("ld.acquire.cta.shared.u32 %0, [%1];" : "=r"(v) : "r"(a) : "memory");
    return v;
}
__device__ __forceinline__ uint4 ll_ld4(const uint4* p) {
    uint4 v;
    asm volatile("ld.volatile.global.v4.u32 {%0,%1,%2,%3}, [%4];"
                 : "=r"(v.x), "=r"(v.y), "=r"(v.z), "=r"(v.w) : "l"(p) : "memory");
    return v;
}
__device__ __forceinline__ void ll_st4(uint4* p, unsigned a, unsigned b2_,
                                       unsigned c, unsigned tag) {
    asm volatile("st.volatile.global.v4.u32 [%0], {%1,%2,%3,%4};"
                 :: "l"(p), "r"(a), "r"(b2_), "r"(c), "r"(tag) : "memory");
}

// ---------------- pre: init state + x_proj ----------------
__global__ void pre_kernel(const float* __restrict__ inp,
                           const float* __restrict__ W_ih,
                           const float* __restrict__ b_ih,
                           const float* __restrict__ b_hh) {
    __shared__ float Wsm[256 * 21];
    __shared__ float bsm[256];
    __shared__ float insm[128 * IN_N];
    int tid = threadIdx.x;
    int r0 = blockIdx.x * 256;
    int t0 = blockIdx.y * 128;

    if (blockIdx.x == 0 && blockIdx.y == 0) {
        uint4* hx = &g_hx4[0][0][0];
        for (int i = tid; i < DEPTH * NREP * GPAD; i += 256)
            hx[i] = make_uint4(0u, 0u, 0u, 0u);  // h(0)=0, tag 0
        for (int i = tid; i < 128; i += 256) g_cnt[i] = 0u;
    }

    for (int i = tid; i < 256 * IN_N; i += 256) {
        int rr = i / IN_N, k = i % IN_N;
        int row = r0 + rr;
        Wsm[rr * 21 + k] = (row < G4) ? W_ih[row * IN_N + k] : 0.f;
    }
    {
        int row = r0 + tid;
        bsm[tid] = (row < G4) ? (b_ih[row] + b_hh[row]) : 0.f;
    }
    for (int i = tid; i < 128 * IN_N; i += 256)
        insm[i] = inp[t0 * IN_N + i];
    __syncthreads();

    int row = r0 + tid;
    if (row < G4) {
        const float* wrow = &Wsm[tid * 21];
        float bias = bsm[tid];
        for (int tt = 0; tt < 128; tt++) {
            const float* ir = &insm[tt * IN_N];
            float acc = bias;
            #pragma unroll
            for (int k = 0; k < IN_N; k++) acc += ir[k] * wrow[k];
            g_xp[(size_t)(t0 + tt) * G4 + row] = acc;
        }
    }
}

// ---------------- persistent LSTM + MLP ----------------
__global__ void __launch_bounds__(NTHREADS, 1)
lstm_kernel(const float* __restrict__ W_hh,
            const float* __restrict__ W1,
            const float* __restrict__ b1,
            const float* __restrict__ W2,
            const float* __restrict__ b2,
            float* __restrict__ out) {
    extern __shared__ float smem[];
    float* Wb_s  = smem;                         // NB * WPAD_B
    float* h_s   = Wb_s + NB * WPAD_B;           // 2 * 1504
    float* part  = h_s + 2 * 1504;               // 4 * 816
    float* xpr   = part + 4 * 816;               // 4 * 48
    float* c_s   = xpr + 4 * NROWS;              // 16
    unsigned* uflag = (unsigned*)(c_s + 16);     // [0] = backpressure bound
    float* hout  = (float*)(uflag + 4);          // 12 fresh h values

    const int tid  = threadIdx.x;
    const int lane = tid & 31;
    const int w    = tid >> 5;
    const int b    = blockIdx.x;
    const int u0   = b * NU;

    const int NK    = (w < 7) ? 24 : 23;
    const int start = (w < 7) ? w * 24 : 168 + (w - 7) * 23;
    const int ubase = start * 4;                 // first unit index of my columns
    const int ucnt  = NK * 4;                    // 92 or 96 units

    // LL128 group range for this warp (groups of 3 units)
    const int g0 = ubase / 3;
    const int ng = (ubase + ucnt + 2) / 3 - g0;  // <= 32 always

    const uint32_t bp_addr = (uint32_t)__cvta_generic_to_shared(uflag);

    // ---- preload plane-B weights (rows 32..47) into smem ----
    for (int idx = tid; idx < NB * 377; idx += NTHREADS) {
        int r = idx / 377, c4 = idx % 377;
        float4 v = make_float4(0.f, 0.f, 0.f, 0.f);
        if (c4 < 375) {
            int lr = 32 + r;
            int grow = (lr / NU) * H_N + u0 + (lr % NU);
            v = *(const float4*)&W_hh[(size_t)grow * H_N + c4 * 4];
        }
        *(float4*)&Wb_s[r * WPAD_B + c4 * 4] = v;
    }
    if (tid < NU) c_s[tid] = 0.f;
    if (tid == 0) uflag[0] = 0u;

    // ---- preload plane-A weights (row = lane, 32 rows) into registers ----
    ulonglong2 wA[NCHUNK];
    {
        int grow = (lane / NU) * H_N + u0 + (lane % NU);
        const float* wrowA = &W_hh[(size_t)grow * H_N];
        #pragma unroll
        for (int k = 0; k < NCHUNK; k++) {
            if (k < NK)
                wA[k] = *(const ulonglong2*)&wrowA[(start + k) * 4];
            else
                wA[k] = make_ulonglong2(0ull, 0ull);
        }
    }

    // plane-B column-split: lanes 0-15 chunks [start,start+12), 16-31 the rest
    const int half   = lane >> 4;
    const int bcnt   = half ? (NK - 12) : 12;
    const float* wbB = &Wb_s[(lane & 15) * WPAD_B + (start + half * 12) * 4];

    // ---- prime cp.async xp ring (steps 0..3) ----
    const uint32_t xr_base = (uint32_t)__cvta_generic_to_shared(xpr);
    const int gate = tid / 3, jj = tid % 3;      // valid for tid<12
    if (tid < 12) {
        #pragma unroll
        for (int tt = 0; tt < 4; tt++) {
            cp_async16(xr_base + (uint32_t)((tt * NROWS + gate * NU + jj * 4) * 4),
                       &g_xp[(size_t)tt * G4 + gate * H_N + u0 + jj * 4]);
            CP_COMMIT();
        }
    }

    __syncthreads();

    for (int t = 0; t < T_STEPS; t++) {
        // warp15 lane0: lazy ring backpressure bound (normally instant)
        if (w == 15 && lane == 0) {
            if (t >= 3) {
                unsigned tgt = (unsigned)NCTA * (unsigned)(t - 2);
                while (ld_acq_g(&g_cnt[0]) < tgt) {}
            }
            st_rel_s(bp_addr, (unsigned)t);
        }

        // ---- LL128 poll+stage: one 16B load per lane ----
        float* hs = h_s + (t & 1) * 1504;
        {
            const uint4* hb = g_hx4[t & 3][b & (NREP - 1)];
            const unsigned tagv = (unsigned)t;
            bool need = (lane < ng);
            do {
                if (need) {
                    uint4 p = ll_ld4(&hb[g0 + lane]);
                    if (p.w == tagv) {
                        float* d = &hs[3 * (g0 + lane)];
                        d[0] = __uint_as_float(p.x);
                        d[1] = __uint_as_float(p.y);
                        d[2] = __uint_as_float(p.z);
                        need = false;
                    }
                }
            } while (!__all_sync(0xffffffffu, !need));
            __syncwarp();
        }

        // ---- matvec: A-plane (32 rows) + split B-plane ----
        unsigned long long aA0 = 0ull, aA1 = 0ull, aB0 = 0ull, aB1 = 0ull;
        const float* hbase = &hs[start * 4];
        #pragma unroll
        for (int k = 0; k < NCHUNK; k++) {
            ulonglong2 hv = (k < NK) ? *(const ulonglong2*)&hbase[k * 4]
                                     : make_ulonglong2(0ull, 0ull);
            FMA2(aA0, wA[k].x, hv.x);
            FMA2(aA1, wA[k].y, hv.y);
        }
        const float* hbB = &hs[(start + half * 12) * 4];
        #pragma unroll
        for (int k = 0; k < 12; k++) {
            bool okk = (k < bcnt);
            ulonglong2 hv = okk ? *(const ulonglong2*)&hbB[k * 4]
                                : make_ulonglong2(0ull, 0ull);
            ulonglong2 wb = okk ? *(const ulonglong2*)&wbB[k * 4]
                                : make_ulonglong2(0ull, 0ull);
            FMA2(aB0, wb.x, hv.x);
            FMA2(aB1, wb.y, hv.y);
        }
        float accA, accB;
        {
            float2 a0 = *(float2*)&aA0, a1 = *(float2*)&aA1;
            accA = (a0.x + a0.y) + (a1.x + a1.y);
            float2 b0 = *(float2*)&aB0, b1 = *(float2*)&aB1;
            accB = (b0.x + b0.y) + (b1.x + b1.y);
        }
        accB += __shfl_xor_sync(0xffffffffu, accB, 16);   // combine column halves
        float* pw = part + (t & 3) * 816;
        pw[lane * 17 + w] = accA;
        if (lane < NB) pw[(32 + lane) * 17 + w] = accB;

        if (w == 0) CP_WAIT3();
        __syncthreads();   // ALL warps: consumption of slot t provably done here

        if (w < 12) {
            // ---- one-round reduce + gates: 4 gates x 8 lanes in parallel ----
            const float* pr  = part + (t & 3) * 816;
            const float* xps = &xpr[(t & 3) * NROWS];
            const int gidx = lane >> 3;          // 0:i 1:f 2:g 3:o
            const int sub  = lane & 7;
            const int row  = gidx * 12 + w;
            float v = pr[row * 17 + sub] + pr[row * 17 + 8 + sub];
            v += __shfl_xor_sync(0xffffffffu, v, 4);
            v += __shfl_xor_sync(0xffffffffu, v, 2);
            v += __shfl_xor_sync(0xffffffffu, v, 1);
            v += xps[row];
            float s = (gidx == 2) ? 2.f : 1.f;   // tanh(x) = 2*sig(2x)-1
            float act = s * __fdividef(1.f, 1.f + __expf(-s * v)) - (s - 1.f);
            float ig = __shfl_sync(0xffffffffu, act, 0);
            float fg = __shfl_sync(0xffffffffu, act, 8);
            float gg = __shfl_sync(0xffffffffu, act, 16);
            float og = __shfl_sync(0xffffffffu, act, 24);
            float c = fg * c_s[w] + ig * gg;
            float hval = og * tanh_f(c);
            if (lane == 0) { c_s[w] = c; hout[w] = hval; }

            asm volatile("bar.sync 1, 384;" ::: "memory");   // 12 unit warps

            // ---- LL128 publish: warps 0-3 = group, lanes 0-3 = replica ----
            if (w < 4 && lane < NREP) {
                float h0 = hout[3 * w + 0];
                float h1 = hout[3 * w + 1];
                float h2 = hout[3 * w + 2];
                while (ld_acq_s(bp_addr) < (unsigned)t) {}
                ll_st4(&g_hx4[(t + 1) & 3][lane][b * 4 + w],
                       __float_as_uint(h0), __float_as_uint(h1),
                       __float_as_uint(h2), (unsigned)(t + 1));
            }
            if (tid == 0) red_rel_g(&g_cnt[0]);              // step-complete arrival
            if (tid < 12) {
                if (t + 4 < T_STEPS)
                    cp_async16(xr_base + (uint32_t)((((t + 4) & 3) * NROWS + gate * NU + jj * 4) * 4),
                               &g_xp[(size_t)(t + 4) * G4 + gate * H_N + u0 + jj * 4]);
                CP_COMMIT();
            }
        }
        // warps 12-15 free-run into the next step's LL128 poll
    }

    // =================== MLP head ===================
    // stage final h(T) into h_s[0] via the same LL128 tag-poll
    {
        float* hs = h_s;
        const uint4* hb = g_hx4[T_STEPS & 3][b & (NREP - 1)];
        const unsigned tagv = (unsigned)T_STEPS;
        bool need = (lane < ng);
        do {
            if (need) {
                uint4 p = ll_ld4(&hb[g0 + lane]);
                if (p.w == tagv) {
                    float* d = &hs[3 * (g0 + lane)];
                    d[0] = __uint_as_float(p.x);
                    d[1] = __uint_as_float(p.y);
                    d[2] = __uint_as_float(p.z);
                    need = false;
                }
            }
        } while (!__all_sync(0xffffffffu, !need));
    }
    __syncthreads();

    {
        int gw = b * 16 + w;
        if (gw < MLP_HID_N) {
            const float* wr = &W1[(size_t)gw * H_N];
            float acc = 0.f;
            for (int c4 = lane; c4 < 375; c4 += 32) {
                float4 wv = *(const float4*)&wr[c4 * 4];
                float4 h4 = *(const float4*)&h_s[c4 * 4];
                acc += wv.x * h4.x + wv.y * h4.y + wv.z * h4.z + wv.w * h4.w;
            }
            acc += __shfl_xor_sync(0xffffffffu, acc, 16);
            acc += __shfl_xor_sync(0xffffffffu, acc, 8);
            acc += __shfl_xor_sync(0xffffffffu, acc, 4);
            acc += __shfl_xor_sync(0xffffffffu, acc, 2);
            acc += __shfl_xor_sync(0xffffffffu, acc, 1);
            if (lane == 0) g_hid[gw] = acc + b1[gw];
        }
        __syncthreads();
        if (tid == 0) red_rel_g(&g_cnt[64]);

        if (b == 0) {
            if (tid == 0) {
                while (ld_acq_g(&g_cnt[64]) < (unsigned)NCTA) {}
            }
            __syncthreads();
            for (int r = w; r < OUT_N; r += 16) {
                const float* wr = &W2[(size_t)r * MLP_HID_N];
                float acc = 0.f;
                for (int c = lane; c < MLP_HID_N; c += 32)
                    acc += wr[c] * __ldcg(&g_hid[c]);
                acc += __shfl_xor_sync(0xffffffffu, acc, 16);
                acc += __shfl_xor_sync(0xffffffffu, acc, 8);
                acc += __shfl_xor_sync(0xffffffffu, acc, 4);
                acc += __shfl_xor_sync(0xffffffffu, acc, 2);
                acc += __shfl_xor_sync(0xffffffffu, acc, 1);
                if (lane == 0) out[r] = acc + b2[r];
            }
        }
    }
}

// ---------------- launch ----------------
extern "C" void kernel_launch(void* const* d_in, const int* in_sizes, int n_in,
                              void* d_out, int out_size) {
    const float* inp  = (const float*)d_in[0];
    const float* W_ih = (const float*)d_in[1];
    const float* W_hh = (const float*)d_in[2];
    const float* b_ih = (const float*)d_in[3];
    const float* b_hh = (const float*)d_in[4];
    const float* W1   = (const float*)d_in[5];
    const float* b1   = (const float*)d_in[6];
    const float* W2   = (const float*)d_in[7];
    const float* b2   = (const float*)d_in[8];
    float* out = (float*)d_out;

    size_t smem_bytes = (size_t)(NB * WPAD_B + 2 * 1504 + 4 * 816 + 4 * NROWS + 16 + 8 + 16)
                        * sizeof(float);
    cudaFuncSetAttribute(lstm_kernel, cudaFuncAttributeMaxDynamicSharedMemorySize,
                         (int)smem_bytes);

    pre_kernel<<<dim3(24, 32), 256>>>(inp, W_ih, b_ih, b_hh);
    lstm_kernel<<<NCTA, NTHREADS, smem_bytes>>>(W_hh, W1, b1, W2, b2, out);
}